// round 2
// baseline (speedup 1.0000x reference)
#include <cuda_runtime.h>
#include <math.h>

#define BB 64
#define LL 2048
#define HH 256
#define BLH (BB*LL*HH)

// Scratch (device globals: allocation-free per harness rules)
__device__ float g_Z[BLH];     // input-transform term per (b,t,h)
__device__ float g_H0[BLH];    // layer-0 hidden states
__device__ int   g_flags[2*BB];

// ---------------------------------------------------------------------------
// reset flags (must run before each recurrence pass; graph replays reuse state)
__global__ __launch_bounds__(128) void reset_flags_k() {
    g_flags[threadIdx.x] = 0;
}

// ---------------------------------------------------------------------------
// GEMM + bias: Out[r][j] = sum_k In[r][k]*W[k][j] + bi[j] + bh[j]
// M = BB*LL = 131072, N = K = 256. Tile 128x128x8, 256 threads, 8x8/thread.
__global__ __launch_bounds__(256) void gemm_bias(
        const float* __restrict__ In, const float* __restrict__ W,
        const float* __restrict__ bi, const float* __restrict__ bh,
        float* __restrict__ Out)
{
    __shared__ float As[8][128];
    __shared__ float Bs[8][128];
    const int tid  = threadIdx.x;
    const int mblk = blockIdx.x * 128;
    const int nblk = blockIdx.y * 128;
    const int tx = tid & 15, ty = tid >> 4;

    const int ar = tid >> 1;          // A row within tile (0..127)
    const int ak = (tid & 1) * 4;     // A k offset (0 or 4)
    const int bk = tid >> 5;          // B k row (0..7)
    const int bc = (tid & 31) * 4;    // B col offset (0..124)

    const float* Arow = In + (size_t)(mblk + ar) * HH;
    float4 a_next = *(const float4*)(Arow + ak);
    float4 b_next = *(const float4*)(W + (size_t)bk * HH + nblk + bc);

    float acc[8][8];
#pragma unroll
    for (int i = 0; i < 8; i++)
#pragma unroll
        for (int j = 0; j < 8; j++) acc[i][j] = 0.f;

    for (int kt = 0; kt < 32; kt++) {
        As[ak + 0][ar] = a_next.x;
        As[ak + 1][ar] = a_next.y;
        As[ak + 2][ar] = a_next.z;
        As[ak + 3][ar] = a_next.w;
        *(float4*)&Bs[bk][bc] = b_next;
        __syncthreads();
        if (kt < 31) {  // prefetch next tiles while computing
            a_next = *(const float4*)(Arow + (kt + 1) * 8 + ak);
            b_next = *(const float4*)(W + (size_t)((kt + 1) * 8 + bk) * HH + nblk + bc);
        }
#pragma unroll
        for (int kk = 0; kk < 8; kk++) {
            float a[8], b[8];
            *(float4*)&a[0] = *(const float4*)&As[kk][ty * 8];
            *(float4*)&a[4] = *(const float4*)&As[kk][ty * 8 + 4];
            *(float4*)&b[0] = *(const float4*)&Bs[kk][tx * 8];
            *(float4*)&b[4] = *(const float4*)&Bs[kk][tx * 8 + 4];
#pragma unroll
            for (int i = 0; i < 8; i++)
#pragma unroll
                for (int j = 0; j < 8; j++) acc[i][j] += a[i] * b[j];
        }
        __syncthreads();
    }

#pragma unroll
    for (int i = 0; i < 8; i++) {
        const size_t r = (size_t)(mblk + ty * 8 + i);
#pragma unroll
        for (int j = 0; j < 8; j += 4) {
            const int c = nblk + tx * 8 + j;
            float4 v;
            v.x = acc[i][j + 0] + bi[c + 0] + bh[c + 0];
            v.y = acc[i][j + 1] + bi[c + 1] + bh[c + 1];
            v.z = acc[i][j + 2] + bi[c + 2] + bh[c + 2];
            v.w = acc[i][j + 3] + bi[c + 3] + bh[c + 3];
            *(float4*)(Out + r * HH + c) = v;
        }
    }
}

// ---------------------------------------------------------------------------
// Persistent recurrence pass for one layer.
// Grid = 128 CTAs: (batch b, column-half). Each CTA holds its 256x128 slice of
// WH in registers (float4 wreg[2][16] per thread = 128 regs), keeps h in SMEM,
// and exchanges the peer half of h through L2 with a monotonic flag.
// Own k-half partial matvec runs BEFORE the peer wait to hide sync latency.
__global__ __launch_bounds__(256, 1) void rnn_pass(
        const float* __restrict__ Z,    // [B,L,H]  z_t = inp@WI + bi + bh
        const float* __restrict__ Wh,   // [H,H]    this layer's WH
        const float* __restrict__ h0,   // [B,H]    initial hidden
        float* __restrict__ Out,        // [B,L,H]  per-step hidden (also exchange medium)
        float* __restrict__ hfinal)     // [B,H] or null
{
    const int b        = blockIdx.x >> 1;
    const int half     = blockIdx.x & 1;
    const int jbase    = half << 7;          // 0 or 128 (own cols == own k-half)
    const int peerbase = 128 - jbase;
    const int tid  = threadIdx.x;
    const int w    = tid >> 5;               // warp 0..7 -> k sub-block
    const int lane = tid & 31;               // lane -> 4 columns
    const int j0   = jbase + lane * 4;

    __shared__ float sh_h[256];
    __shared__ float sacc[8 * 128];

    // Load weight slice into registers.
    float4 wreg[2][16];
    const int kb0 = jbase;      // own k half
    const int kb1 = peerbase;   // peer k half
#pragma unroll
    for (int kk = 0; kk < 16; kk++)
        wreg[0][kk] = *(const float4*)(Wh + (size_t)(kb0 + w * 16 + kk) * HH + j0);
#pragma unroll
    for (int kk = 0; kk < 16; kk++)
        wreg[1][kk] = *(const float4*)(Wh + (size_t)(kb1 + w * 16 + kk) * HH + j0);

    sh_h[tid] = h0[b * HH + tid];
    __syncthreads();

    const int myflag   = blockIdx.x;
    const int peerflag = blockIdx.x ^ 1;
    const float4* shh4 = (const float4*)sh_h;

    for (int t = 0; t < LL; t++) {
        float zv = 0.f;
        if (tid < 128) zv = Z[((size_t)b * LL + t) * HH + jbase + tid];

        float4 acc = make_float4(0.f, 0.f, 0.f, 0.f);

        // ---- phase 1: own k-half (no sync needed) ----
        {
            float hbuf[16];
            const int b4 = (kb0 + w * 16) >> 2;
            *(float4*)&hbuf[0]  = shh4[b4 + 0];
            *(float4*)&hbuf[4]  = shh4[b4 + 1];
            *(float4*)&hbuf[8]  = shh4[b4 + 2];
            *(float4*)&hbuf[12] = shh4[b4 + 3];
#pragma unroll
            for (int kk = 0; kk < 16; kk++) {
                const float hv = hbuf[kk];
                acc.x += wreg[0][kk].x * hv;
                acc.y += wreg[0][kk].y * hv;
                acc.z += wreg[0][kk].z * hv;
                acc.w += wreg[0][kk].w * hv;
            }
        }

        // ---- wait for peer's step t-1 result, pull its h half ----
        if (t > 0) {
            if (tid == 0) {
                while (atomicAdd(&g_flags[peerflag], 0) < t) { __nanosleep(20); }
                __threadfence();   // acquire
            }
            __syncthreads();
            if (tid < 128)
                sh_h[peerbase + tid] =
                    Out[((size_t)b * LL + (t - 1)) * HH + peerbase + tid];
            __syncthreads();
        }

        // ---- phase 2: peer k-half ----
        {
            float hbuf[16];
            const int b4 = (kb1 + w * 16) >> 2;
            *(float4*)&hbuf[0]  = shh4[b4 + 0];
            *(float4*)&hbuf[4]  = shh4[b4 + 1];
            *(float4*)&hbuf[8]  = shh4[b4 + 2];
            *(float4*)&hbuf[12] = shh4[b4 + 3];
#pragma unroll
            for (int kk = 0; kk < 16; kk++) {
                const float hv = hbuf[kk];
                acc.x += wreg[1][kk].x * hv;
                acc.y += wreg[1][kk].y * hv;
                acc.z += wreg[1][kk].z * hv;
                acc.w += wreg[1][kk].w * hv;
            }
        }

        // ---- cross-warp reduction + tanh + publish ----
        *(float4*)&sacc[w * 128 + lane * 4] = acc;
        __syncthreads();
        if (tid < 128) {
            float s = zv;
#pragma unroll
            for (int ww = 0; ww < 8; ww++) s += sacc[ww * 128 + tid];
            const float hv = tanhf(s);
            sh_h[jbase + tid] = hv;                              // own half for t+1
            Out[((size_t)b * LL + t) * HH + jbase + tid] = hv;   // peer reads this
        }
        __syncthreads();
        if (tid == 0) {
            __threadfence();                       // release
            atomicExch(&g_flags[myflag], t + 1);
        }
    }

    if (hfinal && tid < 128)
        hfinal[b * HH + jbase + tid] = sh_h[jbase + tid];
}

// ---------------------------------------------------------------------------
extern "C" void kernel_launch(void* const* d_in, const int* in_sizes, int n_in,
                              void* d_out, int out_size) {
    const float* x  = (const float*)d_in[0];   // [B,L,H]
    const float* h0 = (const float*)d_in[1];   // [NL,B,H]
    const float* WI = (const float*)d_in[2];   // [NL,H,H]
    const float* BI = (const float*)d_in[3];   // [NL,H]
    const float* WH = (const float*)d_in[4];   // [NL,H,H]
    const float* BH = (const float*)d_in[5];   // [NL,H]
    float* out = (float*)d_out;

    float *gZ = nullptr, *gH0 = nullptr;
    cudaGetSymbolAddress((void**)&gZ, g_Z);
    cudaGetSymbolAddress((void**)&gH0, g_H0);

    const dim3 ggrid(BB * LL / 128, HH / 128);  // (1024, 2)

    const bool haveMain  = (out_size >= BLH);
    const bool haveFinal = (out_size >= BLH + 2 * BB * HH);
    float* out2 = haveMain ? out : gZ;                       // layer-1 per-step dest
    float* hf0  = haveFinal ? (out + BLH) : (haveMain ? nullptr : out);
    float* hf1  = haveFinal ? (out + BLH + BB * HH)
                            : (haveMain ? nullptr : out + BB * HH);

    // Phase A: Z0 = X @ WI0 + BI0 + BH0
    reset_flags_k<<<1, 128>>>();
    gemm_bias<<<ggrid, 256>>>(x, WI, BI, BH, gZ);
    // Phase B: layer-0 recurrence
    rnn_pass<<<2 * BB, 256>>>(gZ, WH, h0, gH0, hf0);
    // Phase C: Z1 = H0 @ WI1 + BI1 + BH1  (overwrites gZ)
    reset_flags_k<<<1, 128>>>();
    gemm_bias<<<ggrid, 256>>>(gH0, WI + HH * HH, BI + HH, BH + HH, gZ);
    // Phase D: layer-1 recurrence -> output
    rnn_pass<<<2 * BB, 256>>>(gZ, WH + HH * HH, h0 + BB * HH, out2, hf1);
}

// round 8
// speedup vs baseline: 2.0427x; 2.0427x over previous
#include <cuda_runtime.h>
#include <math.h>
#include <cstdint>

#define BB 64
#define LL 2048
#define HH 256
#define BLH (BB*LL*HH)

// Scratch (device globals: allocation-free per harness rules)
__device__ float g_Z[BLH];     // input-transform term per (b,t,h)
__device__ float g_H0[BLH];    // layer-0 hidden states

// ---------------------------------------------------------------------------
// PTX helpers
__device__ __forceinline__ uint32_t s2u(const void* p) {
    uint32_t a;
    asm("{ .reg .u64 t; cvta.to.shared.u64 t, %1; cvt.u32.u64 %0, t; }"
        : "=r"(a) : "l"(p));
    return a;
}
__device__ __forceinline__ uint32_t mapa_u32(uint32_t addr, uint32_t rank) {
    uint32_t r;
    asm("mapa.shared::cluster.u32 %0, %1, %2;" : "=r"(r) : "r"(addr), "r"(rank));
    return r;
}
__device__ __forceinline__ void mbar_init(uint32_t mbar, uint32_t count) {
    asm volatile("mbarrier.init.shared::cta.b64 [%0], %1;" :: "r"(mbar), "r"(count) : "memory");
}
// Plain remote DSMEM store (peer CTA's SMEM via mapa'd address).
__device__ __forceinline__ void st_remote_f32(uint32_t raddr, float v) {
    asm volatile("st.shared::cluster.f32 [%0], %1;" :: "r"(raddr), "f"(v) : "memory");
}
// Arrive on a peer CTA's mbarrier WITH cluster-scope release: orders this
// thread's prior shared::cluster stores before the arrival becomes visible
// to the peer's acquire-wait. (Default .cta-scope release does NOT — that
// was the R6 race.)
__device__ __forceinline__ void mbar_arrive_remote_release(uint32_t raddr) {
    asm volatile("mbarrier.arrive.release.cluster.shared::cluster.b64 _, [%0];"
                 :: "r"(raddr) : "memory");
}
__device__ __forceinline__ void mbar_wait_parity(uint32_t mbar, uint32_t parity) {
    uint32_t done;
    asm volatile(
        "{\n\t.reg .pred p;\n\t"
        "mbarrier.try_wait.parity.acquire.cluster.shared::cta.b64 p, [%1], %2;\n\t"
        "selp.b32 %0, 1, 0, p;\n\t}"
        : "=r"(done) : "r"(mbar), "r"(parity) : "memory");
    if (!done) {
        asm volatile(
            "{\n\t.reg .pred P1;\n\t"
            "WL_%=:\n\t"
            "mbarrier.try_wait.parity.acquire.cluster.shared::cta.b64 P1, [%0], %1, 0x989680;\n\t"
            "@P1 bra.uni WD_%=;\n\t"
            "bra.uni WL_%=;\n\t"
            "WD_%=:\n\t}"
            :: "r"(mbar), "r"(parity) : "memory");
    }
}
__device__ __forceinline__ void cluster_sync() {
    asm volatile("barrier.cluster.arrive.aligned;" ::: "memory");
    asm volatile("barrier.cluster.wait.aligned;" ::: "memory");
}

// ---------------------------------------------------------------------------
// GEMM + bias: Out[r][j] = sum_k In[r][k]*W[k][j] + bi[j] + bh[j]
// M = BB*LL = 131072, N = K = 256. Tile 128x128x8, 256 threads, 8x8/thread.
__global__ __launch_bounds__(256) void gemm_bias(
        const float* __restrict__ In, const float* __restrict__ W,
        const float* __restrict__ bi, const float* __restrict__ bh,
        float* __restrict__ Out)
{
    __shared__ float As[8][128];
    __shared__ float Bs[8][128];
    const int tid  = threadIdx.x;
    const int mblk = blockIdx.x * 128;
    const int nblk = blockIdx.y * 128;
    const int tx = tid & 15, ty = tid >> 4;

    const int ar = tid >> 1;
    const int ak = (tid & 1) * 4;
    const int bk = tid >> 5;
    const int bc = (tid & 31) * 4;

    const float* Arow = In + (size_t)(mblk + ar) * HH;
    float4 a_next = *(const float4*)(Arow + ak);
    float4 b_next = *(const float4*)(W + (size_t)bk * HH + nblk + bc);

    float acc[8][8];
#pragma unroll
    for (int i = 0; i < 8; i++)
#pragma unroll
        for (int j = 0; j < 8; j++) acc[i][j] = 0.f;

    for (int kt = 0; kt < 32; kt++) {
        As[ak + 0][ar] = a_next.x;
        As[ak + 1][ar] = a_next.y;
        As[ak + 2][ar] = a_next.z;
        As[ak + 3][ar] = a_next.w;
        *(float4*)&Bs[bk][bc] = b_next;
        __syncthreads();
        if (kt < 31) {
            a_next = *(const float4*)(Arow + (kt + 1) * 8 + ak);
            b_next = *(const float4*)(W + (size_t)((kt + 1) * 8 + bk) * HH + nblk + bc);
        }
#pragma unroll
        for (int kk = 0; kk < 8; kk++) {
            float a[8], b[8];
            *(float4*)&a[0] = *(const float4*)&As[kk][ty * 8];
            *(float4*)&a[4] = *(const float4*)&As[kk][ty * 8 + 4];
            *(float4*)&b[0] = *(const float4*)&Bs[kk][tx * 8];
            *(float4*)&b[4] = *(const float4*)&Bs[kk][tx * 8 + 4];
#pragma unroll
            for (int i = 0; i < 8; i++)
#pragma unroll
                for (int j = 0; j < 8; j++) acc[i][j] += a[i] * b[j];
        }
        __syncthreads();
    }

#pragma unroll
    for (int i = 0; i < 8; i++) {
        const size_t r = (size_t)(mblk + ty * 8 + i);
#pragma unroll
        for (int j = 0; j < 8; j += 4) {
            const int c = nblk + tx * 8 + j;
            float4 v;
            v.x = acc[i][j + 0] + bi[c + 0] + bh[c + 0];
            v.y = acc[i][j + 1] + bi[c + 1] + bh[c + 1];
            v.z = acc[i][j + 2] + bi[c + 2] + bh[c + 2];
            v.w = acc[i][j + 3] + bi[c + 3] + bh[c + 3];
            *(float4*)(Out + r * HH + c) = v;
        }
    }
}

// ---------------------------------------------------------------------------
// Persistent recurrence pass for one layer. Cluster of 2 CTAs per batch:
// CTA rank r owns output columns [r*128, r*128+128); its 256x128 WH slice
// lives in registers. h-half exchange goes through DSMEM: plain remote
// stores into the peer's double-buffered recvbuf, then one RELEASE.CLUSTER
// mbarrier arrive per producer warp (count=4). Consumer side pairs with
// acquire.cluster try_wait. Dependency structure bounds skew to 1 step, so
// buffers cannot be overwritten early. Own-half partial matvec runs BEFORE
// the wait so DSMEM latency hides behind ~256 cyc of FFMAs.
__global__ __launch_bounds__(256, 1) __cluster_dims__(2, 1, 1)
void rnn_pass(
        const float* __restrict__ Z,    // [B,L,H]
        const float* __restrict__ Wh,   // [H,H]
        const float* __restrict__ h0,   // [B,H]
        float* __restrict__ Out,        // [B,L,H]
        float* __restrict__ hfinal)     // [B,H] or null
{
    const int b     = blockIdx.x >> 1;
    const int half  = blockIdx.x & 1;            // == cluster rank
    const int jbase = half << 7;                 // own cols == own k-half
    const int peerbase = 128 - jbase;
    const int tid  = threadIdx.x;
    const int w    = tid >> 5;
    const int lane = tid & 31;
    const int j0   = jbase + lane * 4;

    __shared__ float sh_h[256];                  // own half live; peer half used only at t=0
    __shared__ float recvbuf[2][128];            // peer halves, double-buffered
    __shared__ float sacc[8 * 128];
    __shared__ uint64_t mbar[2];

    const uint32_t mbar0 = s2u(&mbar[0]);
    const uint32_t mbar1 = s2u(&mbar[1]);
    const uint32_t rb0   = s2u(&recvbuf[0][0]);
    const uint32_t rb1   = s2u(&recvbuf[1][0]);
    const uint32_t prank = (uint32_t)(half ^ 1);
    const uint32_t p_rb[2]   = { mapa_u32(rb0 + (uint32_t)tid * 4u, prank),
                                 mapa_u32(rb1 + (uint32_t)tid * 4u, prank) };
    const uint32_t p_mbar[2] = { mapa_u32(mbar0, prank), mapa_u32(mbar1, prank) };
    const uint32_t l_mbar[2] = { mbar0, mbar1 };

    if (tid == 0) { mbar_init(mbar0, 4); mbar_init(mbar1, 4); }   // 4 producer warps

    // Weight slice into registers: wreg[0] = own k-half rows, wreg[1] = peer k-half.
    float4 wreg[2][16];
    const int kb0 = jbase, kb1 = peerbase;
#pragma unroll
    for (int kk = 0; kk < 16; kk++)
        wreg[0][kk] = *(const float4*)(Wh + (size_t)(kb0 + w * 16 + kk) * HH + j0);
#pragma unroll
    for (int kk = 0; kk < 16; kk++)
        wreg[1][kk] = *(const float4*)(Wh + (size_t)(kb1 + w * 16 + kk) * HH + j0);

    sh_h[tid] = h0[b * HH + tid];
    __syncthreads();
    cluster_sync();   // mbarrier init visible cluster-wide before any remote arrive

    const float4* shh4 = (const float4*)sh_h;

    // Z prefetch (one step ahead)
    float zv = (tid < 128) ? Z[((size_t)b * LL + 0) * HH + jbase + tid] : 0.f;

    for (int t = 0; t < LL; t++) {
        // Prefetch next step's Z while we compute this one.
        float zv_next = 0.f;
        if (t + 1 < LL && tid < 128)
            zv_next = Z[((size_t)b * LL + (t + 1)) * HH + jbase + tid];

        float4 acc = make_float4(0.f, 0.f, 0.f, 0.f);

        // ---- phase 1: own k-half (local, no wait) ----
        {
            float hbuf[16];
            const int b4 = (kb0 + w * 16) >> 2;
            *(float4*)&hbuf[0]  = shh4[b4 + 0];
            *(float4*)&hbuf[4]  = shh4[b4 + 1];
            *(float4*)&hbuf[8]  = shh4[b4 + 2];
            *(float4*)&hbuf[12] = shh4[b4 + 3];
#pragma unroll
            for (int kk = 0; kk < 16; kk++) {
                const float hv = hbuf[kk];
                acc.x += wreg[0][kk].x * hv;
                acc.y += wreg[0][kk].y * hv;
                acc.z += wreg[0][kk].z * hv;
                acc.w += wreg[0][kk].w * hv;
            }
        }

        // ---- wait for peer half of h_{t-1} (DSMEM push from peer) ----
        const float4* src;
        if (t > 0) {
            mbar_wait_parity(l_mbar[(t - 1) & 1], ((t - 1) >> 1) & 1);
            src = (const float4*)&recvbuf[(t - 1) & 1][0];   // indexed by k - peerbase
        } else {
            src = (const float4*)&sh_h[kb1];                  // h0 peer half
        }

        // ---- phase 2: peer k-half ----
        {
            float hbuf[16];
            const int b4 = (w * 16) >> 2;
            *(float4*)&hbuf[0]  = src[b4 + 0];
            *(float4*)&hbuf[4]  = src[b4 + 1];
            *(float4*)&hbuf[8]  = src[b4 + 2];
            *(float4*)&hbuf[12] = src[b4 + 3];
#pragma unroll
            for (int kk = 0; kk < 16; kk++) {
                const float hv = hbuf[kk];
                acc.x += wreg[1][kk].x * hv;
                acc.y += wreg[1][kk].y * hv;
                acc.z += wreg[1][kk].z * hv;
                acc.w += wreg[1][kk].w * hv;
            }
        }

        // ---- cross-warp reduction + tanh + publish ----
        *(float4*)&sacc[w * 128 + lane * 4] = acc;
        __syncthreads();
        if (tid < 128) {
            float s = zv;
#pragma unroll
            for (int ww = 0; ww < 8; ww++) s += sacc[ww * 128 + tid];
            const float hv = tanhf(s);
            sh_h[jbase + tid] = hv;                                // own half for t+1
            if (t < LL - 1) {
                st_remote_f32(p_rb[t & 1], hv);                    // push to peer buf
                __syncwarp();                                      // warp's stores issued
                if (lane == 0)
                    mbar_arrive_remote_release(p_mbar[t & 1]);     // RELEASE.CLUSTER
            }
            Out[((size_t)b * LL + t) * HH + jbase + tid] = hv;     // result (off chain)
        }
        zv = zv_next;
        __syncthreads();   // protects sh_h own-half and sacc reuse
    }

    if (hfinal && tid < 128)
        hfinal[b * HH + jbase + tid] = sh_h[jbase + tid];

    cluster_sync();   // no CTA exits while peer stores may be in flight
}

// ---------------------------------------------------------------------------
extern "C" void kernel_launch(void* const* d_in, const int* in_sizes, int n_in,
                              void* d_out, int out_size) {
    const float* x  = (const float*)d_in[0];   // [B,L,H]
    const float* h0 = (const float*)d_in[1];   // [NL,B,H]
    const float* WI = (const float*)d_in[2];   // [NL,H,H]
    const float* BI = (const float*)d_in[3];   // [NL,H]
    const float* WH = (const float*)d_in[4];   // [NL,H,H]
    const float* BH = (const float*)d_in[5];   // [NL,H]
    float* out = (float*)d_out;

    float *gZ = nullptr, *gH0 = nullptr;
    cudaGetSymbolAddress((void**)&gZ, g_Z);
    cudaGetSymbolAddress((void**)&gH0, g_H0);

    const dim3 ggrid(BB * LL / 128, HH / 128);  // (1024, 2)

    const bool haveMain  = (out_size >= BLH);
    const bool haveFinal = (out_size >= BLH + 2 * BB * HH);
    float* out2 = haveMain ? out : gZ;
    float* hf0  = haveFinal ? (out + BLH) : (haveMain ? nullptr : out);
    float* hf1  = haveFinal ? (out + BLH + BB * HH)
                            : (haveMain ? nullptr : out + BB * HH);

    // Phase A: Z0 = X @ WI0 + BI0 + BH0
    gemm_bias<<<ggrid, 256>>>(x, WI, BI, BH, gZ);
    // Phase B: layer-0 recurrence (64 clusters x 2 CTAs)
    rnn_pass<<<2 * BB, 256>>>(gZ, WH, h0, gH0, hf0);
    // Phase C: Z1 = H0 @ WI1 + BI1 + BH1
    gemm_bias<<<ggrid, 256>>>(gH0, WI + HH * HH, BI + HH, BH + HH, gZ);
    // Phase D: layer-1 recurrence -> output
    rnn_pass<<<2 * BB, 256>>>(gZ, WH + HH * HH, h0 + BB * HH, out2, hf1);
}